// round 2
// baseline (speedup 1.0000x reference)
#include <cuda_runtime.h>
#include <math.h>

#define BB   4
#define SS   1024
#define DD   512
#define HH   8
#define DKK  64
#define KTOP 204
#define PDIM 64
#define NPAT 8

// ---- scratch (static device arrays; no allocation in kernel_launch) ----
__device__ float g_Qf[BB*SS*DD];
__device__ float g_Kf[BB*SS*DD];
__device__ float g_Vf[BB*SS*DD];
__device__ float g_Ctx[BB*SS*DD];
__device__ float g_H1[BB*SS*PDIM];
__device__ float g_Enc[BB*SS*PDIM];
__device__ float g_Sc[(size_t)BB*HH*SS*SS];   // per-head scores -> probs (in place)
__device__ float g_S3[(size_t)BB*SS*SS];      // full-dim scores (flat 512-chain)

// ---------------- generic GEMM: C = act(A @ W + bias) ----------------
// A: MxK row-major, W: KxN row-major. ACT: 0 none, 1 relu, 2 tanh.
// Accumulates each output as a single ascending-k FMA chain (matches sgemm).
template<int ACT>
__global__ __launch_bounds__(256)
void gemm_bias_kernel(const float* __restrict__ A, const float* __restrict__ W,
                      const float* __restrict__ bias, float* __restrict__ C,
                      int M, int N, int K) {
    __shared__ float As[16][65];  // [k][m]
    __shared__ float Bs[16][65];  // [k][n]
    int tid = threadIdx.x;
    int tx = tid & 15, ty = tid >> 4;
    int m0 = blockIdx.y * 64, n0 = blockIdx.x * 64;
    float acc[4][4] = {};
    for (int k0 = 0; k0 < K; k0 += 16) {
        #pragma unroll
        for (int l = 0; l < 4; l++) {
            int idx = tid + l * 256;
            int r = idx >> 4, c = idx & 15;           // A: 64x16
            As[c][r] = A[(size_t)(m0 + r) * K + k0 + c];
        }
        #pragma unroll
        for (int l = 0; l < 4; l++) {
            int idx = tid + l * 256;
            int r = idx >> 6, c = idx & 63;           // W: 16x64
            Bs[r][c] = W[(size_t)(k0 + r) * N + n0 + c];
        }
        __syncthreads();
        #pragma unroll
        for (int kk = 0; kk < 16; kk++) {
            float a[4], b[4];
            #pragma unroll
            for (int i = 0; i < 4; i++) a[i] = As[kk][ty * 4 + i];
            #pragma unroll
            for (int j = 0; j < 4; j++) b[j] = Bs[kk][tx * 4 + j];
            #pragma unroll
            for (int i = 0; i < 4; i++)
                #pragma unroll
                for (int j = 0; j < 4; j++)
                    acc[i][j] = fmaf(a[i], b[j], acc[i][j]);
        }
        __syncthreads();
    }
    #pragma unroll
    for (int i = 0; i < 4; i++) {
        int m = m0 + ty * 4 + i;
        #pragma unroll
        for (int j = 0; j < 4; j++) {
            int n = n0 + tx * 4 + j;
            float v = acc[i][j] + bias[n];
            if (ACT == 1) v = fmaxf(v, 0.0f);
            if (ACT == 2) v = tanhf(v);
            C[(size_t)m * N + n] = v;
        }
    }
}

// ------------- per-head scores + full-dim flat-chain sum: Sc, S3 -------------
// S3[b,i,j] is accumulated as ONE fp32 FMA chain in strictly ascending k
// (k = h*64 + kk), bit-matching a flat sgemm over K=512.
__global__ __launch_bounds__(256)
void scores_kernel(const float* __restrict__ Qf, const float* __restrict__ Kf,
                   float* __restrict__ Sc, float* __restrict__ S3) {
    __shared__ float Qs[64][65];
    __shared__ float Ks[64][65];
    int b = blockIdx.z;
    int i0 = blockIdx.y * 64, j0 = blockIdx.x * 64;
    int tid = threadIdx.x, tx = tid & 15, ty = tid >> 4;
    float s3[4][4] = {};
    for (int h = 0; h < HH; h++) {
        #pragma unroll
        for (int l = 0; l < 16; l++) {
            int idx = tid + l * 256;
            int r = idx >> 6, c = idx & 63;
            Qs[r][c] = Qf[(size_t)(b * SS + i0 + r) * DD + h * 64 + c];
            Ks[r][c] = Kf[(size_t)(b * SS + j0 + r) * DD + h * 64 + c];
        }
        __syncthreads();
        float acc[4][4] = {};
        #pragma unroll
        for (int k = 0; k < 64; k++) {
            float a[4], v[4];
            #pragma unroll
            for (int i = 0; i < 4; i++) a[i] = Qs[ty * 4 + i][k];
            #pragma unroll
            for (int j = 0; j < 4; j++) v[j] = Ks[tx * 4 + j][k];
            #pragma unroll
            for (int i = 0; i < 4; i++)
                #pragma unroll
                for (int j = 0; j < 4; j++) {
                    acc[i][j] = fmaf(a[i], v[j], acc[i][j]);   // per-head 64-chain
                    s3[i][j]  = fmaf(a[i], v[j], s3[i][j]);    // flat 512-chain
                }
        }
        size_t base = (((size_t)(b * HH + h) * SS + i0) * SS) + j0;
        #pragma unroll
        for (int i = 0; i < 4; i++)
            #pragma unroll
            for (int j = 0; j < 4; j++)
                Sc[base + (size_t)(ty * 4 + i) * SS + tx * 4 + j] = acc[i][j] * 0.125f;
        __syncthreads();
    }
    size_t b3 = ((size_t)b * SS + i0) * SS + j0;
    #pragma unroll
    for (int i = 0; i < 4; i++)
        #pragma unroll
        for (int j = 0; j < 4; j++)
            S3[b3 + (size_t)(ty * 4 + i) * SS + tx * 4 + j] = s3[i][j] * 0.125f;
}

// ------------- row-wise top-204 (total order, ties by lowest index) -> mask -------------
__global__ __launch_bounds__(256)
void topk_mask_kernel(const float* __restrict__ S3, float* __restrict__ maskOut) {
    __shared__ unsigned keys[1024];
    __shared__ int hist[256];
    __shared__ unsigned s_prefix;
    __shared__ int s_rem;
    int row = blockIdx.x;          // b*SS + i
    int b = row >> 10, i = row & 1023;
    int tid = threadIdx.x;
    const float* src = S3 + (size_t)row * SS;
    #pragma unroll
    for (int l = 0; l < 4; l++) {
        int j = tid + l * 256;
        unsigned bits = __float_as_uint(src[j]);
        keys[j] = (bits & 0x80000000u) ? ~bits : (bits | 0x80000000u);
    }
    if (tid == 0) { s_prefix = 0u; s_rem = KTOP; }
    __syncthreads();
    for (int pass = 0; pass < 4; pass++) {
        int shift = 24 - pass * 8;
        hist[tid] = 0;
        __syncthreads();
        unsigned pref = s_prefix;
        #pragma unroll
        for (int l = 0; l < 4; l++) {
            unsigned key = keys[tid + l * 256];
            bool match = (pass == 0) || ((key >> (shift + 8)) == (pref >> (shift + 8)));
            if (match) atomicAdd(&hist[(key >> shift) & 255], 1);
        }
        __syncthreads();
        if (tid == 0) {
            int c = 0, rem = s_rem; unsigned chosen = 0;
            for (int bin = 255; bin >= 0; bin--) {
                c += hist[bin];
                if (c >= rem) { chosen = (unsigned)bin; s_rem = rem - (c - hist[bin]); break; }
            }
            s_prefix = pref | (chosen << shift);
        }
        __syncthreads();
    }
    unsigned T = s_prefix;
    int need = s_rem;
    size_t maskBase = (size_t)b * HH * SS * SS + (size_t)i * SS;
    #pragma unroll
    for (int l = 0; l < 4; l++) {
        int j = tid + l * 256;
        unsigned key = keys[j];
        float m = 0.0f;
        if (key > T) m = 1.0f;
        else if (key == T) {
            int cnt = 0;
            for (int jj = 0; jj < j; jj++) cnt += (keys[jj] == T) ? 1 : 0;
            if (cnt < need) m = 1.0f;
        }
        #pragma unroll
        for (int h = 0; h < HH; h++)
            maskOut[maskBase + (size_t)h * SS * SS + j] = m;
    }
}

// ------------- masked softmax in place on Sc -------------
__global__ __launch_bounds__(256)
void softmax_kernel(float* __restrict__ Sc, const float* __restrict__ maskOut) {
    __shared__ float red[8];
    __shared__ float sval;
    int row = blockIdx.x;          // (b*H + h)*S + i
    int tid = threadIdx.x;
    float* sc = Sc + (size_t)row * SS;
    const float* mk = maskOut + (size_t)row * SS;
    float4 s = ((const float4*)sc)[tid];
    float4 m = ((const float4*)mk)[tid];
    float vmax = -1e30f;
    if (m.x > 0.0f) vmax = fmaxf(vmax, s.x);
    if (m.y > 0.0f) vmax = fmaxf(vmax, s.y);
    if (m.z > 0.0f) vmax = fmaxf(vmax, s.z);
    if (m.w > 0.0f) vmax = fmaxf(vmax, s.w);
    #pragma unroll
    for (int o = 16; o > 0; o >>= 1) vmax = fmaxf(vmax, __shfl_xor_sync(0xffffffffu, vmax, o));
    if ((tid & 31) == 0) red[tid >> 5] = vmax;
    __syncthreads();
    if (tid == 0) {
        float v = red[0];
        #pragma unroll
        for (int k = 1; k < 8; k++) v = fmaxf(v, red[k]);
        sval = v;
    }
    __syncthreads();
    vmax = sval;
    __syncthreads();
    float4 e;
    e.x = (m.x > 0.0f) ? expf(s.x - vmax) : 0.0f;
    e.y = (m.y > 0.0f) ? expf(s.y - vmax) : 0.0f;
    e.z = (m.z > 0.0f) ? expf(s.z - vmax) : 0.0f;
    e.w = (m.w > 0.0f) ? expf(s.w - vmax) : 0.0f;
    float lsum = e.x + e.y + e.z + e.w;
    #pragma unroll
    for (int o = 16; o > 0; o >>= 1) lsum += __shfl_xor_sync(0xffffffffu, lsum, o);
    if ((tid & 31) == 0) red[tid >> 5] = lsum;
    __syncthreads();
    if (tid == 0) {
        float v = 0.0f;
        #pragma unroll
        for (int k = 0; k < 8; k++) v += red[k];
        sval = v;
    }
    __syncthreads();
    float denom = sval;
    float4 p;
    p.x = e.x / denom; p.y = e.y / denom; p.z = e.z / denom; p.w = e.w / denom;
    ((float4*)sc)[tid] = p;
}

// ------------- Ctx[b,i,h*64+d] = P[b,h,i,:] @ Vh[b,h,:,d] -------------
__global__ __launch_bounds__(256)
void av_kernel(const float* __restrict__ P, const float* __restrict__ Vf,
               float* __restrict__ Ctx) {
    __shared__ float Ps[64][65];
    __shared__ float Vs[64][65];
    int bh = blockIdx.y;
    int b = bh >> 3, h = bh & 7;
    int i0 = blockIdx.x * 64;
    int tid = threadIdx.x, tx = tid & 15, ty = tid >> 4;
    float acc[4][4] = {};
    const float* Prow = P + ((size_t)bh * SS + i0) * SS;
    for (int k0 = 0; k0 < SS; k0 += 64) {
        #pragma unroll
        for (int l = 0; l < 16; l++) {
            int idx = tid + l * 256;
            int r = idx >> 6, c = idx & 63;
            Ps[r][c] = Prow[(size_t)r * SS + k0 + c];
            Vs[r][c] = Vf[(size_t)(b * SS + k0 + r) * DD + h * 64 + c];
        }
        __syncthreads();
        #pragma unroll 16
        for (int kk = 0; kk < 64; kk++) {
            float a[4], v[4];
            #pragma unroll
            for (int i = 0; i < 4; i++) a[i] = Ps[ty * 4 + i][kk];
            #pragma unroll
            for (int j = 0; j < 4; j++) v[j] = Vs[kk][tx * 4 + j];
            #pragma unroll
            for (int i = 0; i < 4; i++)
                #pragma unroll
                for (int j = 0; j < 4; j++)
                    acc[i][j] = fmaf(a[i], v[j], acc[i][j]);
        }
        __syncthreads();
    }
    #pragma unroll
    for (int i = 0; i < 4; i++)
        #pragma unroll
        for (int j = 0; j < 4; j++)
            Ctx[(size_t)(b * SS + i0 + ty * 4 + i) * DD + h * 64 + tx * 4 + j] = acc[i][j];
}

// ------------- pattern head: softmax(enc@bank^T/8) * gate -------------
__global__ __launch_bounds__(256)
void pattern_kernel(const float* __restrict__ Enc, const float* __restrict__ bank,
                    const float* __restrict__ gate, float* __restrict__ outP) {
    int r = blockIdx.x * blockDim.x + threadIdx.x;
    if (r >= BB * SS) return;
    const float* e = Enc + (size_t)r * PDIM;
    float s[NPAT];
    float mx = -1e30f;
    #pragma unroll
    for (int p = 0; p < NPAT; p++) {
        float d = 0.0f;
        for (int k = 0; k < PDIM; k++) d = fmaf(e[k], bank[p * PDIM + k], d);
        s[p] = d * 0.125f;
        mx = fmaxf(mx, s[p]);
    }
    float sum = 0.0f;
    #pragma unroll
    for (int p = 0; p < NPAT; p++) { s[p] = expf(s[p] - mx); sum += s[p]; }
    #pragma unroll
    for (int p = 0; p < NPAT; p++)
        outP[(size_t)r * NPAT + p] = s[p] / sum * gate[p];
}

extern "C" void kernel_launch(void* const* d_in, const int* in_sizes, int n_in,
                              void* d_out, int out_size) {
    const float* query = (const float*)d_in[0];
    const float* key   = (const float*)d_in[1];
    const float* value = (const float*)d_in[2];
    const float* wq = (const float*)d_in[3];  const float* bq = (const float*)d_in[4];
    const float* wk = (const float*)d_in[5];  const float* bk = (const float*)d_in[6];
    const float* wv = (const float*)d_in[7];  const float* bv = (const float*)d_in[8];
    const float* wo = (const float*)d_in[9];  const float* bo = (const float*)d_in[10];
    const float* pw1 = (const float*)d_in[11]; const float* pb1 = (const float*)d_in[12];
    const float* pw2 = (const float*)d_in[13]; const float* pb2 = (const float*)d_in[14];
    const float* bank = (const float*)d_in[15];
    const float* gate = (const float*)d_in[16];
    float* out = (float*)d_out;

    void *pQf, *pKf, *pVf, *pCtx, *pH1, *pEnc, *pSc, *pS3;
    cudaGetSymbolAddress(&pQf, g_Qf);
    cudaGetSymbolAddress(&pKf, g_Kf);
    cudaGetSymbolAddress(&pVf, g_Vf);
    cudaGetSymbolAddress(&pCtx, g_Ctx);
    cudaGetSymbolAddress(&pH1, g_H1);
    cudaGetSymbolAddress(&pEnc, g_Enc);
    cudaGetSymbolAddress(&pSc, g_Sc);
    cudaGetSymbolAddress(&pS3, g_S3);
    float* Qf = (float*)pQf;   float* Kf = (float*)pKf;
    float* Vf = (float*)pVf;   float* Ctx = (float*)pCtx;
    float* H1 = (float*)pH1;   float* Enc = (float*)pEnc;
    float* Sc = (float*)pSc;   float* S3 = (float*)pS3;

    const size_t outOff   = 0;
    const size_t maskOff  = (size_t)BB * SS * DD;                       // 2,097,152
    const size_t patOff   = maskOff + (size_t)BB * HH * SS * SS;        // 35,651,584
    float* outAttn = out + outOff;
    float* outMask = out + maskOff;
    float* outPat  = out + patOff;

    const int M = BB * SS;   // 4096
    dim3 blk(256);

    // QKV projections
    gemm_bias_kernel<0><<<dim3(DD / 64, M / 64), blk>>>(query, wq, bq, Qf, M, DD, DD);
    gemm_bias_kernel<0><<<dim3(DD / 64, M / 64), blk>>>(key,   wk, bk, Kf, M, DD, DD);
    gemm_bias_kernel<0><<<dim3(DD / 64, M / 64), blk>>>(value, wv, bv, Vf, M, DD, DD);

    // pattern MLP
    gemm_bias_kernel<1><<<dim3(PDIM / 64, M / 64), blk>>>(query, pw1, pb1, H1, M, PDIM, DD);
    gemm_bias_kernel<2><<<dim3(PDIM / 64, M / 64), blk>>>(H1, pw2, pb2, Enc, M, PDIM, PDIM);
    pattern_kernel<<<dim3(M / 256), blk>>>(Enc, bank, gate, outPat);

    // per-head scores + flat-chain full-dim scores
    scores_kernel<<<dim3(SS / 64, SS / 64, BB), blk>>>(Qf, Kf, Sc, S3);

    // top-204 mask, broadcast across heads
    topk_mask_kernel<<<dim3(BB * SS), blk>>>(S3, outMask);

    // masked softmax in place
    softmax_kernel<<<dim3(BB * HH * SS), blk>>>(Sc, outMask);

    // attn @ V
    av_kernel<<<dim3(SS / 64, BB * HH), blk>>>(Sc, Vf, Ctx);

    // output projection
    gemm_bias_kernel<0><<<dim3(DD / 64, M / 64), blk>>>(Ctx, wo, bo, outAttn, M, DD, DD);
}

// round 3
// speedup vs baseline: 1.0991x; 1.0991x over previous
#include <cuda_runtime.h>
#include <math.h>

#define BB   4
#define SS   1024
#define DD   512
#define HH   8
#define DKK  64
#define KTOP 204
#define PDIM 64
#define NPAT 8

// ---- scratch (static device arrays; no allocation in kernel_launch) ----
__device__ float g_Qf[BB*SS*DD];
__device__ float g_Kf[BB*SS*DD];
__device__ float g_Vf[BB*SS*DD];
__device__ float g_Ctx[BB*SS*DD];
__device__ float g_H1[BB*SS*PDIM];
__device__ float g_Enc[BB*SS*PDIM];
__device__ float g_Sc[(size_t)BB*HH*SS*SS];   // per-head scores -> probs (in place)
__device__ float g_S3[(size_t)BB*SS*SS];      // full-dim scores (flat 512-chain)

// ---- packed f32x2 helpers (sm_103a): 2 IEEE fp32 FMAs per instruction ----
__device__ __forceinline__ unsigned long long ff2_pack(float lo, float hi) {
    unsigned long long r;
    asm("mov.b64 %0, {%1, %2};" : "=l"(r) : "f"(lo), "f"(hi));
    return r;
}
__device__ __forceinline__ unsigned long long ff2_fma(unsigned long long a,
                                                      unsigned long long b,
                                                      unsigned long long c) {
    unsigned long long d;
    asm("fma.rn.f32x2 %0, %1, %2, %3;" : "=l"(d) : "l"(a), "l"(b), "l"(c));
    return d;
}
__device__ __forceinline__ float2 ff2_unpack(unsigned long long v) {
    float lo, hi;
    asm("mov.b64 {%0, %1}, %2;" : "=f"(lo), "=f"(hi) : "l"(v));
    return make_float2(lo, hi);
}

// ---------------- generic GEMM: C = act(A @ W + bias) ----------------
// A: MxK row-major, W: KxN row-major. ACT: 0 none, 1 relu, 2 tanh.
// Each output element is ONE ascending-k fp32 FMA chain (bit-matches sgemm);
// f32x2 packs two independent chains per instruction.
template<int ACT>
__global__ __launch_bounds__(256)
void gemm_bias_kernel(const float* __restrict__ A, const float* __restrict__ W,
                      const float* __restrict__ bias, float* __restrict__ C,
                      int M, int N, int K) {
    __shared__ __align__(16) float As[16][68];  // [k][m], 272B row stride (16B aligned)
    __shared__ __align__(16) float Bs[16][68];  // [k][n]
    int tid = threadIdx.x;
    int tx = tid & 15, ty = tid >> 4;
    int m0 = blockIdx.y * 64, n0 = blockIdx.x * 64;
    unsigned long long acc2[4][2];
    #pragma unroll
    for (int i = 0; i < 4; i++) { acc2[i][0] = 0ull; acc2[i][1] = 0ull; }
    for (int k0 = 0; k0 < K; k0 += 16) {
        #pragma unroll
        for (int l = 0; l < 4; l++) {
            int idx = tid + l * 256;
            int r = idx >> 4, c = idx & 15;           // A: 64x16
            As[c][r] = A[(size_t)(m0 + r) * K + k0 + c];
        }
        #pragma unroll
        for (int l = 0; l < 4; l++) {
            int idx = tid + l * 256;
            int r = idx >> 6, c = idx & 63;           // W: 16x64
            Bs[r][c] = W[(size_t)(k0 + r) * N + n0 + c];
        }
        __syncthreads();
        #pragma unroll
        for (int kk = 0; kk < 16; kk++) {
            float4 a4 = *(const float4*)&As[kk][ty * 4];
            float4 b4 = *(const float4*)&Bs[kk][tx * 4];
            unsigned long long b01 = ff2_pack(b4.x, b4.y);
            unsigned long long b23 = ff2_pack(b4.z, b4.w);
            unsigned long long aa;
            aa = ff2_pack(a4.x, a4.x);
            acc2[0][0] = ff2_fma(aa, b01, acc2[0][0]);
            acc2[0][1] = ff2_fma(aa, b23, acc2[0][1]);
            aa = ff2_pack(a4.y, a4.y);
            acc2[1][0] = ff2_fma(aa, b01, acc2[1][0]);
            acc2[1][1] = ff2_fma(aa, b23, acc2[1][1]);
            aa = ff2_pack(a4.z, a4.z);
            acc2[2][0] = ff2_fma(aa, b01, acc2[2][0]);
            acc2[2][1] = ff2_fma(aa, b23, acc2[2][1]);
            aa = ff2_pack(a4.w, a4.w);
            acc2[3][0] = ff2_fma(aa, b01, acc2[3][0]);
            acc2[3][1] = ff2_fma(aa, b23, acc2[3][1]);
        }
        __syncthreads();
    }
    #pragma unroll
    for (int i = 0; i < 4; i++) {
        int m = m0 + ty * 4 + i;
        #pragma unroll
        for (int jp = 0; jp < 2; jp++) {
            float2 v2 = ff2_unpack(acc2[i][jp]);
            int n = n0 + tx * 4 + jp * 2;
            float v = v2.x + bias[n];
            if (ACT == 1) v = fmaxf(v, 0.0f);
            if (ACT == 2) v = tanhf(v);
            C[(size_t)m * N + n] = v;
            v = v2.y + bias[n + 1];
            if (ACT == 1) v = fmaxf(v, 0.0f);
            if (ACT == 2) v = tanhf(v);
            C[(size_t)m * N + n + 1] = v;
        }
    }
}

// ------------- per-head scores + full-dim flat-chain sum: Sc, S3 -------------
// S3[b,i,j]: ONE fp32 FMA chain in strictly ascending k (k = h*64 + kk),
// bit-matching a flat sgemm over K=512 (load-bearing for the top-k mask).
__global__ __launch_bounds__(256)
void scores_kernel(const float* __restrict__ Qf, const float* __restrict__ Kf,
                   float* __restrict__ Sc, float* __restrict__ S3) {
    __shared__ float Qs[64][65];
    __shared__ float Ks[64][65];
    int b = blockIdx.z;
    int i0 = blockIdx.y * 64, j0 = blockIdx.x * 64;
    int tid = threadIdx.x, tx = tid & 15, ty = tid >> 4;
    unsigned long long s32[4][2];
    #pragma unroll
    for (int i = 0; i < 4; i++) { s32[i][0] = 0ull; s32[i][1] = 0ull; }
    for (int h = 0; h < HH; h++) {
        #pragma unroll
        for (int l = 0; l < 16; l++) {
            int idx = tid + l * 256;
            int r = idx >> 6, c = idx & 63;
            Qs[r][c] = Qf[(size_t)(b * SS + i0 + r) * DD + h * 64 + c];
            Ks[r][c] = Kf[(size_t)(b * SS + j0 + r) * DD + h * 64 + c];
        }
        __syncthreads();
        unsigned long long acc2[4][2];
        #pragma unroll
        for (int i = 0; i < 4; i++) { acc2[i][0] = 0ull; acc2[i][1] = 0ull; }
        #pragma unroll
        for (int k = 0; k < 64; k++) {
            float a0 = Qs[ty * 4 + 0][k], a1 = Qs[ty * 4 + 1][k];
            float a2 = Qs[ty * 4 + 2][k], a3 = Qs[ty * 4 + 3][k];
            float v0 = Ks[tx * 4 + 0][k], v1 = Ks[tx * 4 + 1][k];
            float v2 = Ks[tx * 4 + 2][k], v3 = Ks[tx * 4 + 3][k];
            unsigned long long b01 = ff2_pack(v0, v1);
            unsigned long long b23 = ff2_pack(v2, v3);
            unsigned long long aa;
            aa = ff2_pack(a0, a0);
            acc2[0][0] = ff2_fma(aa, b01, acc2[0][0]);
            acc2[0][1] = ff2_fma(aa, b23, acc2[0][1]);
            s32[0][0]  = ff2_fma(aa, b01, s32[0][0]);
            s32[0][1]  = ff2_fma(aa, b23, s32[0][1]);
            aa = ff2_pack(a1, a1);
            acc2[1][0] = ff2_fma(aa, b01, acc2[1][0]);
            acc2[1][1] = ff2_fma(aa, b23, acc2[1][1]);
            s32[1][0]  = ff2_fma(aa, b01, s32[1][0]);
            s32[1][1]  = ff2_fma(aa, b23, s32[1][1]);
            aa = ff2_pack(a2, a2);
            acc2[2][0] = ff2_fma(aa, b01, acc2[2][0]);
            acc2[2][1] = ff2_fma(aa, b23, acc2[2][1]);
            s32[2][0]  = ff2_fma(aa, b01, s32[2][0]);
            s32[2][1]  = ff2_fma(aa, b23, s32[2][1]);
            aa = ff2_pack(a3, a3);
            acc2[3][0] = ff2_fma(aa, b01, acc2[3][0]);
            acc2[3][1] = ff2_fma(aa, b23, acc2[3][1]);
            s32[3][0]  = ff2_fma(aa, b01, s32[3][0]);
            s32[3][1]  = ff2_fma(aa, b23, s32[3][1]);
        }
        size_t base = (((size_t)(b * HH + h) * SS + i0) * SS) + j0;
        #pragma unroll
        for (int i = 0; i < 4; i++)
            #pragma unroll
            for (int jp = 0; jp < 2; jp++) {
                float2 v2 = ff2_unpack(acc2[i][jp]);
                size_t o = base + (size_t)(ty * 4 + i) * SS + tx * 4 + jp * 2;
                Sc[o]     = v2.x * 0.125f;
                Sc[o + 1] = v2.y * 0.125f;
            }
        __syncthreads();
    }
    size_t b3 = ((size_t)b * SS + i0) * SS + j0;
    #pragma unroll
    for (int i = 0; i < 4; i++)
        #pragma unroll
        for (int jp = 0; jp < 2; jp++) {
            float2 v2 = ff2_unpack(s32[i][jp]);
            size_t o = b3 + (size_t)(ty * 4 + i) * SS + tx * 4 + jp * 2;
            S3[o]     = v2.x * 0.125f;
            S3[o + 1] = v2.y * 0.125f;
        }
}

// ------------- row-wise top-204 (total order, ties by lowest index) -> mask -------------
__global__ __launch_bounds__(256)
void topk_mask_kernel(const float* __restrict__ S3, float* __restrict__ maskOut) {
    __shared__ unsigned keys[1024];
    __shared__ int hist[256];
    __shared__ unsigned s_prefix;
    __shared__ int s_rem;
    int row = blockIdx.x;          // b*SS + i
    int b = row >> 10, i = row & 1023;
    int tid = threadIdx.x;
    const float* src = S3 + (size_t)row * SS;
    #pragma unroll
    for (int l = 0; l < 4; l++) {
        int j = tid + l * 256;
        unsigned bits = __float_as_uint(src[j]);
        keys[j] = (bits & 0x80000000u) ? ~bits : (bits | 0x80000000u);
    }
    if (tid == 0) { s_prefix = 0u; s_rem = KTOP; }
    __syncthreads();
    for (int pass = 0; pass < 4; pass++) {
        int shift = 24 - pass * 8;
        hist[tid] = 0;
        __syncthreads();
        unsigned pref = s_prefix;
        #pragma unroll
        for (int l = 0; l < 4; l++) {
            unsigned key = keys[tid + l * 256];
            bool match = (pass == 0) || ((key >> (shift + 8)) == (pref >> (shift + 8)));
            if (match) atomicAdd(&hist[(key >> shift) & 255], 1);
        }
        __syncthreads();
        if (tid == 0) {
            int c = 0, rem = s_rem; unsigned chosen = 0;
            for (int bin = 255; bin >= 0; bin--) {
                c += hist[bin];
                if (c >= rem) { chosen = (unsigned)bin; s_rem = rem - (c - hist[bin]); break; }
            }
            s_prefix = pref | (chosen << shift);
        }
        __syncthreads();
    }
    unsigned T = s_prefix;
    int need = s_rem;
    size_t maskBase = (size_t)b * HH * SS * SS + (size_t)i * SS;
    #pragma unroll
    for (int l = 0; l < 4; l++) {
        int j = tid + l * 256;
        unsigned key = keys[j];
        float m = 0.0f;
        if (key > T) m = 1.0f;
        else if (key == T) {
            int cnt = 0;
            for (int jj = 0; jj < j; jj++) cnt += (keys[jj] == T) ? 1 : 0;
            if (cnt < need) m = 1.0f;
        }
        #pragma unroll
        for (int h = 0; h < HH; h++)
            maskOut[maskBase + (size_t)h * SS * SS + j] = m;
    }
}

// ------------- masked softmax in place on Sc -------------
__global__ __launch_bounds__(256)
void softmax_kernel(float* __restrict__ Sc, const float* __restrict__ maskOut) {
    __shared__ float red[8];
    __shared__ float sval;
    int row = blockIdx.x;          // (b*H + h)*S + i
    int tid = threadIdx.x;
    float* sc = Sc + (size_t)row * SS;
    const float* mk = maskOut + (size_t)row * SS;
    float4 s = ((const float4*)sc)[tid];
    float4 m = ((const float4*)mk)[tid];
    float vmax = -1e30f;
    if (m.x > 0.0f) vmax = fmaxf(vmax, s.x);
    if (m.y > 0.0f) vmax = fmaxf(vmax, s.y);
    if (m.z > 0.0f) vmax = fmaxf(vmax, s.z);
    if (m.w > 0.0f) vmax = fmaxf(vmax, s.w);
    #pragma unroll
    for (int o = 16; o > 0; o >>= 1) vmax = fmaxf(vmax, __shfl_xor_sync(0xffffffffu, vmax, o));
    if ((tid & 31) == 0) red[tid >> 5] = vmax;
    __syncthreads();
    if (tid == 0) {
        float v = red[0];
        #pragma unroll
        for (int k = 1; k < 8; k++) v = fmaxf(v, red[k]);
        sval = v;
    }
    __syncthreads();
    vmax = sval;
    __syncthreads();
    float4 e;
    e.x = (m.x > 0.0f) ? expf(s.x - vmax) : 0.0f;
    e.y = (m.y > 0.0f) ? expf(s.y - vmax) : 0.0f;
    e.z = (m.z > 0.0f) ? expf(s.z - vmax) : 0.0f;
    e.w = (m.w > 0.0f) ? expf(s.w - vmax) : 0.0f;
    float lsum = e.x + e.y + e.z + e.w;
    #pragma unroll
    for (int o = 16; o > 0; o >>= 1) lsum += __shfl_xor_sync(0xffffffffu, lsum, o);
    if ((tid & 31) == 0) red[tid >> 5] = lsum;
    __syncthreads();
    if (tid == 0) {
        float v = 0.0f;
        #pragma unroll
        for (int k = 0; k < 8; k++) v += red[k];
        sval = v;
    }
    __syncthreads();
    float denom = sval;
    float4 p;
    p.x = e.x / denom; p.y = e.y / denom; p.z = e.z / denom; p.w = e.w / denom;
    ((float4*)sc)[tid] = p;
}

// ------------- Ctx[b,i,h*64+d] = P[b,h,i,:] @ Vh[b,h,:,d] -------------
__global__ __launch_bounds__(256)
void av_kernel(const float* __restrict__ P, const float* __restrict__ Vf,
               float* __restrict__ Ctx) {
    __shared__ float Ps[64][65];
    __shared__ __align__(16) float Vs[64][68];
    int bh = blockIdx.y;
    int b = bh >> 3, h = bh & 7;
    int i0 = blockIdx.x * 64;
    int tid = threadIdx.x, tx = tid & 15, ty = tid >> 4;
    unsigned long long acc2[4][2];
    #pragma unroll
    for (int i = 0; i < 4; i++) { acc2[i][0] = 0ull; acc2[i][1] = 0ull; }
    const float* Prow = P + ((size_t)bh * SS + i0) * SS;
    for (int k0 = 0; k0 < SS; k0 += 64) {
        #pragma unroll
        for (int l = 0; l < 16; l++) {
            int idx = tid + l * 256;
            int r = idx >> 6, c = idx & 63;
            Ps[r][c] = Prow[(size_t)r * SS + k0 + c];
            Vs[r][c] = Vf[(size_t)(b * SS + k0 + r) * DD + h * 64 + c];
        }
        __syncthreads();
        #pragma unroll 16
        for (int kk = 0; kk < 64; kk++) {
            float a0 = Ps[ty * 4 + 0][kk], a1 = Ps[ty * 4 + 1][kk];
            float a2 = Ps[ty * 4 + 2][kk], a3 = Ps[ty * 4 + 3][kk];
            float4 v4 = *(const float4*)&Vs[kk][tx * 4];
            unsigned long long b01 = ff2_pack(v4.x, v4.y);
            unsigned long long b23 = ff2_pack(v4.z, v4.w);
            unsigned long long aa;
            aa = ff2_pack(a0, a0);
            acc2[0][0] = ff2_fma(aa, b01, acc2[0][0]);
            acc2[0][1] = ff2_fma(aa, b23, acc2[0][1]);
            aa = ff2_pack(a1, a1);
            acc2[1][0] = ff2_fma(aa, b01, acc2[1][0]);
            acc2[1][1] = ff2_fma(aa, b23, acc2[1][1]);
            aa = ff2_pack(a2, a2);
            acc2[2][0] = ff2_fma(aa, b01, acc2[2][0]);
            acc2[2][1] = ff2_fma(aa, b23, acc2[2][1]);
            aa = ff2_pack(a3, a3);
            acc2[3][0] = ff2_fma(aa, b01, acc2[3][0]);
            acc2[3][1] = ff2_fma(aa, b23, acc2[3][1]);
        }
        __syncthreads();
    }
    #pragma unroll
    for (int i = 0; i < 4; i++)
        #pragma unroll
        for (int jp = 0; jp < 2; jp++) {
            float2 v2 = ff2_unpack(acc2[i][jp]);
            size_t o = (size_t)(b * SS + i0 + ty * 4 + i) * DD + h * 64 + tx * 4 + jp * 2;
            Ctx[o]     = v2.x;
            Ctx[o + 1] = v2.y;
        }
}

// ------------- pattern head: softmax(enc@bank^T/8) * gate -------------
__global__ __launch_bounds__(256)
void pattern_kernel(const float* __restrict__ Enc, const float* __restrict__ bank,
                    const float* __restrict__ gate, float* __restrict__ outP) {
    int r = blockIdx.x * blockDim.x + threadIdx.x;
    if (r >= BB * SS) return;
    const float* e = Enc + (size_t)r * PDIM;
    float s[NPAT];
    float mx = -1e30f;
    #pragma unroll
    for (int p = 0; p < NPAT; p++) {
        float d = 0.0f;
        for (int k = 0; k < PDIM; k++) d = fmaf(e[k], bank[p * PDIM + k], d);
        s[p] = d * 0.125f;
        mx = fmaxf(mx, s[p]);
    }
    float sum = 0.0f;
    #pragma unroll
    for (int p = 0; p < NPAT; p++) { s[p] = expf(s[p] - mx); sum += s[p]; }
    #pragma unroll
    for (int p = 0; p < NPAT; p++)
        outP[(size_t)r * NPAT + p] = s[p] / sum * gate[p];
}

extern "C" void kernel_launch(void* const* d_in, const int* in_sizes, int n_in,
                              void* d_out, int out_size) {
    const float* query = (const float*)d_in[0];
    const float* key   = (const float*)d_in[1];
    const float* value = (const float*)d_in[2];
    const float* wq = (const float*)d_in[3];  const float* bq = (const float*)d_in[4];
    const float* wk = (const float*)d_in[5];  const float* bk = (const float*)d_in[6];
    const float* wv = (const float*)d_in[7];  const float* bv = (const float*)d_in[8];
    const float* wo = (const float*)d_in[9];  const float* bo = (const float*)d_in[10];
    const float* pw1 = (const float*)d_in[11]; const float* pb1 = (const float*)d_in[12];
    const float* pw2 = (const float*)d_in[13]; const float* pb2 = (const float*)d_in[14];
    const float* bank = (const float*)d_in[15];
    const float* gate = (const float*)d_in[16];
    float* out = (float*)d_out;

    void *pQf, *pKf, *pVf, *pCtx, *pH1, *pEnc, *pSc, *pS3;
    cudaGetSymbolAddress(&pQf, g_Qf);
    cudaGetSymbolAddress(&pKf, g_Kf);
    cudaGetSymbolAddress(&pVf, g_Vf);
    cudaGetSymbolAddress(&pCtx, g_Ctx);
    cudaGetSymbolAddress(&pH1, g_H1);
    cudaGetSymbolAddress(&pEnc, g_Enc);
    cudaGetSymbolAddress(&pSc, g_Sc);
    cudaGetSymbolAddress(&pS3, g_S3);
    float* Qf = (float*)pQf;   float* Kf = (float*)pKf;
    float* Vf = (float*)pVf;   float* Ctx = (float*)pCtx;
    float* H1 = (float*)pH1;   float* Enc = (float*)pEnc;
    float* Sc = (float*)pSc;   float* S3 = (float*)pS3;

    const size_t maskOff  = (size_t)BB * SS * DD;                       // 2,097,152
    const size_t patOff   = maskOff + (size_t)BB * HH * SS * SS;        // 35,651,584
    float* outAttn = out;
    float* outMask = out + maskOff;
    float* outPat  = out + patOff;

    const int M = BB * SS;   // 4096
    dim3 blk(256);

    // QKV projections (bit-exact chains — load-bearing for the mask)
    gemm_bias_kernel<0><<<dim3(DD / 64, M / 64), blk>>>(query, wq, bq, Qf, M, DD, DD);
    gemm_bias_kernel<0><<<dim3(DD / 64, M / 64), blk>>>(key,   wk, bk, Kf, M, DD, DD);
    gemm_bias_kernel<0><<<dim3(DD / 64, M / 64), blk>>>(value, wv, bv, Vf, M, DD, DD);

    // pattern MLP
    gemm_bias_kernel<1><<<dim3(PDIM / 64, M / 64), blk>>>(query, pw1, pb1, H1, M, PDIM, DD);
    gemm_bias_kernel<2><<<dim3(PDIM / 64, M / 64), blk>>>(H1, pw2, pb2, Enc, M, PDIM, PDIM);
    pattern_kernel<<<dim3(M / 256), blk>>>(Enc, bank, gate, outPat);

    // per-head scores + flat-chain full-dim scores
    scores_kernel<<<dim3(SS / 64, SS / 64, BB), blk>>>(Qf, Kf, Sc, S3);

    // top-204 mask, broadcast across heads
    topk_mask_kernel<<<dim3(BB * SS), blk>>>(S3, outMask);

    // masked softmax in place
    softmax_kernel<<<dim3(BB * HH * SS), blk>>>(Sc, outMask);

    // attn @ V
    av_kernel<<<dim3(SS / 64, BB * HH), blk>>>(Sc, Vf, Ctx);

    // output projection
    gemm_bias_kernel<0><<<dim3(DD / 64, M / 64), blk>>>(Ctx, wo, bo, outAttn, M, DD, DD);
}